// round 6
// baseline (speedup 1.0000x reference)
#include <cuda_runtime.h>
#include <math.h>

#define T_LEN 8192
#define NT 768
#define XS 36          // padded row stride: 16B-aligned, phase-conflict-free (4-word rotation)
#define SESTR 104

// float offsets in dynamic smem
#define OFF_X   0          // 77 x XS
#define OFF_RB  2772       // 76 x XS
#define OFF_GT  5508       // 75 x XS
#define OFF_WB  8208       // 3 weight buffers of WBSZ
#define WBSZ    8192
// inside a weight buffer
#define WDO 0              // 64 x XS
#define WFO 2304
#define WGO 4608
#define WRO 6912           // 32 x XS
#define BSO 8064           // 128 biases
#define SMEM_FLOATS (OFF_WB + 3*WBSZ)   // 32784 floats = 131136 B

typedef unsigned long long u64;

__device__ __forceinline__ u64 pack2(float lo, float hi) {
    u64 r; asm("mov.b64 %0,{%1,%2};" : "=l"(r) : "f"(lo), "f"(hi)); return r;
}
__device__ __forceinline__ u64 dup2(float x) { return pack2(x, x); }
__device__ __forceinline__ void fma2(u64& a, u64 w, u64 x) {
    asm("fma.rn.f32x2 %0,%1,%2,%0;" : "+l"(a) : "l"(w), "l"(x));
}
__device__ __forceinline__ u64 add2(u64 a, u64 b) {
    u64 r; asm("add.rn.f32x2 %0,%1,%2;" : "=l"(r) : "l"(a), "l"(b)); return r;
}
__device__ __forceinline__ float2 unpk(u64 a) {
    float2 f; asm("mov.b64 {%0,%1},%2;" : "=f"(f.x), "=f"(f.y) : "l"(a)); return f;
}
__device__ __forceinline__ float warp_sum(float v) {
    #pragma unroll
    for (int o = 16; o; o >>= 1) v += __shfl_xor_sync(0xffffffffu, v, o);
    return v;
}
__device__ __forceinline__ float fast_tanh(float x) {
    float e = __expf(-2.0f * x);
    return fmaf(2.0f, __frcp_rn(1.0f + e), -1.0f);
}
__device__ __forceinline__ float fast_sig(float x) {
    return __frcp_rn(1.0f + __expf(-x));
}
__device__ __forceinline__ float dot4(float4 a, float4 b) {
    return fmaf(a.x, b.x, fmaf(a.y, b.y, fmaf(a.z, b.z, a.w * b.w)));
}

__global__ void __launch_bounds__(NT, 1) wavenet_kernel(
    const int*   __restrict__ tokens,
    const float* __restrict__ emb,
    const float* __restrict__ init_w, const float* __restrict__ init_b,
    const float* __restrict__ dil_w,  const float* __restrict__ dil_b,
    const float* __restrict__ filt_w, const float* __restrict__ filt_b,
    const float* __restrict__ gate_w, const float* __restrict__ gate_b,
    const float* __restrict__ res_w,  const float* __restrict__ res_b,
    const float* __restrict__ skip_w, const float* __restrict__ skip_b,
    const float* __restrict__ end1_w, const float* __restrict__ end1_b,
    const float* __restrict__ end2_w, const float* __restrict__ end2_b,
    const float* __restrict__ fc1_w,  const float* __restrict__ fc1_b,
    const float* __restrict__ fc2_w,  const float* __restrict__ fc2_b,
    const float* __restrict__ fc3_w,  const float* __restrict__ fc3_b,
    const float* __restrict__ fc4_w,  const float* __restrict__ fc4_b,
    float* __restrict__ out)
{
    extern __shared__ float sm[];
    __shared__ int stok[77];

    float* X  = sm + OFF_X;
    float* RB = sm + OFF_RB;
    float* GT = sm + OFF_GT;

    const int b    = blockIdx.x;
    const int tid  = threadIdx.x;
    const int lane = tid & 31;
    const int warp = tid >> 5;
    // compute warps 0..15: 8 channel groups of 4, 2 position groups
    const int cg   = warp & 7;
    const int pg   = (warp >> 3) & 1;
    const int cb   = cg * 4;
    const int u0   = lane + 32 * pg;   // 0..63
    const int u1   = u0 + 64;          // 64..127
    const int s    = tid - 512;        // staging thread id (warps 16-23)

    // ---- staging helper: layer li -> weight buffer bi (threads 512..767) ----
    auto stage = [&](int li, int bi) {
        float* B = sm + OFF_WB + bi * WBSZ;
        const float* gd = dil_w  + li * 2048;
        const float* gf = filt_w + li * 2048;
        const float* gg = gate_w + li * 2048;
        const float* gr = res_w  + li * 1024;
        #pragma unroll
        for (int k = 0; k < 8; k++) {
            int t = s + 256 * k;
            int c = t >> 6, rk = t & 63;
            int o = rk * XS + c;
            B[WDO + o] = __ldg(gd + t);
            B[WFO + o] = __ldg(gf + t);
            B[WGO + o] = __ldg(gg + t);
        }
        #pragma unroll
        for (int k = 0; k < 4; k++) {
            int t = s + 256 * k;
            B[WRO + (t & 31) * XS + (t >> 5)] = __ldg(gr + t);
        }
        if (s < 128) {
            int q = s >> 5, i = s & 31;
            const float* bp = (q == 0) ? dil_b : (q == 1) ? filt_b : (q == 2) ? gate_b : res_b;
            B[BSO + s] = __ldg(bp + li * 32 + i);
        }
    };

    // ================= init: split work between warp groups ===============
    if (warp < 16) {
        if (tid < 77) stok[tid] = tokens[b * T_LEN + (T_LEN - 77) + tid];
        float* WI = RB;                      // [e][c] stride XS (3600 fl, spills into GT scratch)
        for (int t = tid; t < 3200; t += 512)
            WI[(t % 100) * XS + (t / 100)] = init_w[t];
        asm volatile("bar.sync 1, 512;");
        float* SE = sm + OFF_WB + 2 * WBSZ;  // [p][e] stride SESTR in buf2 (8008 fl)
        for (int t = tid; t < 7700; t += 512) {
            int p = t / 100, e = t - p * 100;
            SE[p * SESTR + e] = emb[stok[p] * 100 + e];
        }
        asm volatile("bar.sync 1, 512;");
        {
            const int v1 = (u1 < 77);
            const int uu1 = v1 ? u1 : 0;
            u64 a0 = pack2(init_b[cb],   init_b[cb+1]);
            u64 a1 = pack2(init_b[cb+2], init_b[cb+3]);
            u64 b0 = a0, b1 = a1;
            const float* xr0 = &SE[u0  * SESTR];
            const float* xr1 = &SE[uu1 * SESTR];
            #pragma unroll 5
            for (int e = 0; e < 100; e += 4) {
                float4 x0 = *(const float4*)(xr0 + e);
                float4 x1 = *(const float4*)(xr1 + e);
                #pragma unroll
                for (int ee = 0; ee < 4; ee++) {
                    u64 d0 = dup2((&x0.x)[ee]);
                    u64 d1 = dup2((&x1.x)[ee]);
                    const float* w = &WI[(e + ee) * XS + cb];
                    ulonglong2 Wv = *(const ulonglong2*)w;
                    fma2(a0, Wv.x, d0); fma2(a1, Wv.y, d0);
                    fma2(b0, Wv.x, d1); fma2(b1, Wv.y, d1);
                }
            }
            { ulonglong2 t0; t0.x = a0; t0.y = a1; *(ulonglong2*)&X[u0*XS + cb] = t0; }
            if (v1) { ulonglong2 t0; t0.x = b0; t0.y = b1; *(ulonglong2*)&X[u1*XS + cb] = t0; }
        }
    } else {
        stage(0, 0);        // layer 0 -> buf0
        stage(1, 1);        // layer 1 -> buf1
    }
    __syncthreads();

    // ================= 16 dilated layers =================================
    int W = 75;
    int cur = 0;            // li % 3
    #pragma unroll 1
    for (int li = 0; li < 16; li++) {
        const int d = 1 << (li & 3);
        if (li) W -= d + 1;

        float* WB  = sm + OFF_WB + cur * WBSZ;
        const float* WD  = WB + WDO;
        const float* WF  = WB + WFO;
        const float* WG  = WB + WGO;
        const float* WRs = WB + WRO;
        const float* BS  = WB + BSO;

        // staging warps: prefetch layer li+2 while compute runs
        if (warp >= 16 && li < 14) {
            int bi = cur + 2; if (bi >= 3) bi -= 3;
            stage(li + 2, bi);
        }

        // ---- dilated conv -> RB, u in [0, W] ----
        if (warp < 16) {
            const int v0 = (u0 <= W), v1 = (u1 <= W);
            const int uu0 = v0 ? u0 : 0, uu1 = v1 ? u1 : 0;
            u64 a0 = pack2(BS[cb], BS[cb+1]);
            u64 a1 = pack2(BS[cb+2], BS[cb+3]);
            u64 b0 = a0, b1 = a1;
            const float* p00 = &X[uu0*XS];
            const float* p01 = &X[(uu0 + d)*XS];
            const float* p10 = &X[uu1*XS];
            const float* p11 = &X[(uu1 + d)*XS];
            #pragma unroll
            for (int r = 0; r < 32; r += 4) {
                float4 xa0 = *(const float4*)(p00 + r);
                float4 xb0 = *(const float4*)(p01 + r);
                float4 xa1 = *(const float4*)(p10 + r);
                float4 xb1 = *(const float4*)(p11 + r);
                #pragma unroll
                for (int rr = 0; rr < 4; rr++) {
                    const float* w = &WD[(2*(r + rr))*XS + cb];
                    ulonglong2 W0 = *(const ulonglong2*)w;        // tap 0, 4 ch
                    ulonglong2 W1 = *(const ulonglong2*)(w + XS); // tap 1
                    u64 d00 = dup2((&xa0.x)[rr]), d01 = dup2((&xb0.x)[rr]);
                    u64 d10 = dup2((&xa1.x)[rr]), d11 = dup2((&xb1.x)[rr]);
                    fma2(a0, W0.x, d00); fma2(a1, W0.y, d00);
                    fma2(a0, W1.x, d01); fma2(a1, W1.y, d01);
                    fma2(b0, W0.x, d10); fma2(b1, W0.y, d10);
                    fma2(b0, W1.x, d11); fma2(b1, W1.y, d11);
                }
            }
            if (v0) { ulonglong2 t0; t0.x = a0; t0.y = a1; *(ulonglong2*)&RB[u0*XS + cb] = t0; }
            if (v1) { ulonglong2 t0; t0.x = b0; t0.y = b1; *(ulonglong2*)&RB[u1*XS + cb] = t0; }
        }
        __syncthreads();

        // ---- filter & gate convs + activation + product -> GT, u in [0, W) ----
        if (warp < 16) {
            const int v0 = (u0 < W), v1 = (u1 < W);
            const int uu0 = v0 ? u0 : 0, uu1 = v1 ? u1 : 0;
            u64 f0 = pack2(BS[32+cb], BS[32+cb+1]);
            u64 f1 = pack2(BS[32+cb+2], BS[32+cb+3]);
            u64 g0 = pack2(BS[64+cb], BS[64+cb+1]);
            u64 g1 = pack2(BS[64+cb+2], BS[64+cb+3]);
            u64 h0 = f0, h1 = f1;   // pos1 filter
            u64 k0 = g0, k1 = g1;   // pos1 gate
            const float* p00 = &RB[uu0*XS];
            const float* p01 = &RB[(uu0 + 1)*XS];
            const float* p10 = &RB[uu1*XS];
            const float* p11 = &RB[(uu1 + 1)*XS];
            #pragma unroll
            for (int r = 0; r < 32; r += 4) {
                float4 xa0 = *(const float4*)(p00 + r);
                float4 xb0 = *(const float4*)(p01 + r);
                float4 xa1 = *(const float4*)(p10 + r);
                float4 xb1 = *(const float4*)(p11 + r);
                #pragma unroll
                for (int rr = 0; rr < 4; rr++) {
                    u64 d00 = dup2((&xa0.x)[rr]), d01 = dup2((&xb0.x)[rr]);
                    u64 d10 = dup2((&xa1.x)[rr]), d11 = dup2((&xb1.x)[rr]);
                    const float* wf = &WF[(2*(r + rr))*XS + cb];
                    ulonglong2 F0 = *(const ulonglong2*)wf;
                    ulonglong2 F1 = *(const ulonglong2*)(wf + XS);
                    fma2(f0, F0.x, d00); fma2(f1, F0.y, d00);
                    fma2(f0, F1.x, d01); fma2(f1, F1.y, d01);
                    fma2(h0, F0.x, d10); fma2(h1, F0.y, d10);
                    fma2(h0, F1.x, d11); fma2(h1, F1.y, d11);
                    const float* wg = &WG[(2*(r + rr))*XS + cb];
                    ulonglong2 G0 = *(const ulonglong2*)wg;
                    ulonglong2 G1 = *(const ulonglong2*)(wg + XS);
                    fma2(g0, G0.x, d00); fma2(g1, G0.y, d00);
                    fma2(g0, G1.x, d01); fma2(g1, G1.y, d01);
                    fma2(k0, G0.x, d10); fma2(k1, G0.y, d10);
                    fma2(k0, G1.x, d11); fma2(k1, G1.y, d11);
                }
            }
            if (v0) {
                float2 Fa = unpk(f0), Fb = unpk(f1);
                float2 Ga = unpk(g0), Gb = unpk(g1);
                float4 o;
                o.x = fast_tanh(Fa.x) * fast_sig(Ga.x);
                o.y = fast_tanh(Fa.y) * fast_sig(Ga.y);
                o.z = fast_tanh(Fb.x) * fast_sig(Gb.x);
                o.w = fast_tanh(Fb.y) * fast_sig(Gb.y);
                *(float4*)&GT[u0*XS + cb] = o;
            }
            if (v1) {
                float2 Fa = unpk(h0), Fb = unpk(h1);
                float2 Ga = unpk(k0), Gb = unpk(k1);
                float4 o;
                o.x = fast_tanh(Fa.x) * fast_sig(Ga.x);
                o.y = fast_tanh(Fa.y) * fast_sig(Ga.y);
                o.z = fast_tanh(Fb.x) * fast_sig(Gb.x);
                o.w = fast_tanh(Fb.y) * fast_sig(Gb.y);
                *(float4*)&GT[u1*XS + cb] = o;
            }
        }
        __syncthreads();

        // ---- res 1x1 conv + residual add -> X, u in [0, W) ----
        if (li < 15) {
            if (warp < 16) {
                const int v0 = (u0 < W), v1 = (u1 < W);
                const int uu0 = v0 ? u0 : 0, uu1 = v1 ? u1 : 0;
                u64 a0 = pack2(BS[96+cb], BS[96+cb+1]);
                u64 a1 = pack2(BS[96+cb+2], BS[96+cb+3]);
                u64 b0 = a0, b1 = a1;
                const float* p0 = &GT[uu0*XS];
                const float* p1 = &GT[uu1*XS];
                #pragma unroll
                for (int r = 0; r < 32; r += 4) {
                    float4 xa0 = *(const float4*)(p0 + r);
                    float4 xa1 = *(const float4*)(p1 + r);
                    #pragma unroll
                    for (int rr = 0; rr < 4; rr++) {
                        u64 d0 = dup2((&xa0.x)[rr]);
                        u64 d1 = dup2((&xa1.x)[rr]);
                        ulonglong2 Wv = *(const ulonglong2*)&WRs[(r + rr)*XS + cb];
                        fma2(a0, Wv.x, d0); fma2(a1, Wv.y, d0);
                        fma2(b0, Wv.x, d1); fma2(b1, Wv.y, d1);
                    }
                }
                if (v0) {
                    ulonglong2 rv = *(const ulonglong2*)&RB[u0*XS + cb];
                    ulonglong2 t0; t0.x = add2(a0, rv.x); t0.y = add2(a1, rv.y);
                    *(ulonglong2*)&X[u0*XS + cb] = t0;
                }
                if (v1) {
                    ulonglong2 rv = *(const ulonglong2*)&RB[u1*XS + cb];
                    ulonglong2 t0; t0.x = add2(b0, rv.x); t0.y = add2(b1, rv.y);
                    *(ulonglong2*)&X[u1*XS + cb] = t0;
                }
            }
            __syncthreads();
        }
        cur++; if (cur == 3) cur = 0;
    }

    // ================= tail: skip/end/fc at t = T-1 only =================
    float* SV = RB;        // relu(skip) 256
    float* H1 = RB + 256;  // 256
    float* H2 = RB + 512;  // 256
    float* F1 = RB + 768;  // 128
    float* F2 = RB + 896;  // 128
    float* F3 = RB + 1024; // 64

    const float* skw = skip_w + 15*256*32;
    const float* skb = skip_b + 15*256;
    float gv = GT[lane];
    #pragma unroll 2
    for (int o = warp; o < 256; o += 24) {
        float v = __ldg(&skw[o*32 + lane]) * gv;
        v = warp_sum(v);
        if (lane == 0) SV[o] = fmaxf(v + skb[o], 0.f);
    }
    __syncthreads();
    #pragma unroll 2
    for (int o = warp; o < 256; o += 24) {
        const float4* wp = (const float4*)(end1_w + o*256);
        const float4* sp = (const float4*)SV;
        float v = dot4(__ldg(wp + lane), sp[lane]) + dot4(__ldg(wp + lane + 32), sp[lane + 32]);
        v = warp_sum(v);
        if (lane == 0) H1[o] = fmaxf(v + end1_b[o], 0.f);
    }
    __syncthreads();
    #pragma unroll 2
    for (int o = warp; o < 256; o += 24) {
        const float4* wp = (const float4*)(end2_w + o*256);
        const float4* sp = (const float4*)H1;
        float v = dot4(__ldg(wp + lane), sp[lane]) + dot4(__ldg(wp + lane + 32), sp[lane + 32]);
        v = warp_sum(v);
        if (lane == 0) H2[o] = v + end2_b[o];
    }
    __syncthreads();
    #pragma unroll 2
    for (int o = warp; o < 128; o += 24) {
        const float4* wp = (const float4*)(fc1_w + o*256);
        const float4* sp = (const float4*)H2;
        float v = dot4(__ldg(wp + lane), sp[lane]) + dot4(__ldg(wp + lane + 32), sp[lane + 32]);
        v = warp_sum(v);
        if (lane == 0) F1[o] = fmaxf(v + fc1_b[o], 0.f);
    }
    __syncthreads();
    #pragma unroll 2
    for (int o = warp; o < 128; o += 24) {
        const float4* wp = (const float4*)(fc2_w + o*128);
        const float4* sp = (const float4*)F1;
        float v = dot4(__ldg(wp + lane), sp[lane]);
        v = warp_sum(v);
        if (lane == 0) F2[o] = fmaxf(v + fc2_b[o], 0.f);
    }
    __syncthreads();
    #pragma unroll 2
    for (int o = warp; o < 64; o += 24) {
        const float4* wp = (const float4*)(fc3_w + o*128);
        const float4* sp = (const float4*)F2;
        float v = dot4(__ldg(wp + lane), sp[lane]);
        v = warp_sum(v);
        if (lane == 0) F3[o] = fmaxf(v + fc3_b[o], 0.f);
    }
    __syncthreads();
    #pragma unroll 2
    for (int o = warp; o < 256; o += 24) {
        const float2* wp = (const float2*)(fc4_w + o*64);
        const float2* sp = (const float2*)F3;
        float2 wv = __ldg(wp + lane);
        float2 sv = sp[lane];
        float v = fmaf(wv.x, sv.x, wv.y * sv.y);
        v = warp_sum(v);
        if (lane == 0) out[b*256 + o] = v + fc4_b[o];
    }
}

extern "C" void kernel_launch(void* const* d_in, const int* in_sizes, int n_in,
                              void* d_out, int out_size)
{
    (void)in_sizes; (void)n_in; (void)out_size;
    const size_t smem_bytes = (size_t)SMEM_FLOATS * sizeof(float);
    cudaFuncSetAttribute(wavenet_kernel, cudaFuncAttributeMaxDynamicSharedMemorySize,
                         (int)smem_bytes);
    wavenet_kernel<<<16, NT, smem_bytes>>>(
        (const int*)  d_in[0],  (const float*)d_in[1],
        (const float*)d_in[2],  (const float*)d_in[3],
        (const float*)d_in[4],  (const float*)d_in[5],
        (const float*)d_in[6],  (const float*)d_in[7],
        (const float*)d_in[8],  (const float*)d_in[9],
        (const float*)d_in[10], (const float*)d_in[11],
        (const float*)d_in[12], (const float*)d_in[13],
        (const float*)d_in[14], (const float*)d_in[15],
        (const float*)d_in[16], (const float*)d_in[17],
        (const float*)d_in[18], (const float*)d_in[19],
        (const float*)d_in[20], (const float*)d_in[21],
        (const float*)d_in[22], (const float*)d_in[23],
        (const float*)d_in[24], (const float*)d_in[25],
        (float*)d_out);
}

// round 7
// speedup vs baseline: 1.1770x; 1.1770x over previous
#include <cuda_runtime.h>
#include <math.h>

#define T_LEN 8192
#define NT 768
#define XS 36          // padded row stride: 16B-aligned, phase-conflict-free (4-word rotation)
#define SESTR 104

// float offsets in dynamic smem
#define OFF_X   0          // 77 x XS
#define OFF_RB  2772       // 76 x XS
#define OFF_GT  5508       // 75 x XS
#define OFF_WB  8208       // 3 weight buffers of WBSZ
#define WBSZ    8192
// inside a weight buffer
#define WDO 0              // 64 x XS
#define WFO 2304
#define WGO 4608
#define WRO 6912           // 32 x XS
#define BSO 8064           // 128 biases
#define SMEM_FLOATS (OFF_WB + 3*WBSZ)   // 32784 floats = 131136 B

typedef unsigned long long u64;

__device__ __forceinline__ u64 pack2(float lo, float hi) {
    u64 r; asm("mov.b64 %0,{%1,%2};" : "=l"(r) : "f"(lo), "f"(hi)); return r;
}
__device__ __forceinline__ u64 dup2(float x) { return pack2(x, x); }
__device__ __forceinline__ void fma2(u64& a, u64 w, u64 x) {
    asm("fma.rn.f32x2 %0,%1,%2,%0;" : "+l"(a) : "l"(w), "l"(x));
}
__device__ __forceinline__ u64 add2(u64 a, u64 b) {
    u64 r; asm("add.rn.f32x2 %0,%1,%2;" : "=l"(r) : "l"(a), "l"(b)); return r;
}
__device__ __forceinline__ float2 unpk(u64 a) {
    float2 f; asm("mov.b64 {%0,%1},%2;" : "=f"(f.x), "=f"(f.y) : "l"(a)); return f;
}
__device__ __forceinline__ float warp_sum(float v) {
    #pragma unroll
    for (int o = 16; o; o >>= 1) v += __shfl_xor_sync(0xffffffffu, v, o);
    return v;
}
__device__ __forceinline__ float fast_tanh(float x) {
    float e = __expf(-2.0f * x);
    return fmaf(2.0f, __frcp_rn(1.0f + e), -1.0f);
}
__device__ __forceinline__ float fast_sig(float x) {
    return __frcp_rn(1.0f + __expf(-x));
}
__device__ __forceinline__ float dot4(float4 a, float4 b) {
    return fmaf(a.x, b.x, fmaf(a.y, b.y, fmaf(a.z, b.z, a.w * b.w)));
}

__global__ void __launch_bounds__(NT, 1) wavenet_kernel(
    const int*   __restrict__ tokens,
    const float* __restrict__ emb,
    const float* __restrict__ init_w, const float* __restrict__ init_b,
    const float* __restrict__ dil_w,  const float* __restrict__ dil_b,
    const float* __restrict__ filt_w, const float* __restrict__ filt_b,
    const float* __restrict__ gate_w, const float* __restrict__ gate_b,
    const float* __restrict__ res_w,  const float* __restrict__ res_b,
    const float* __restrict__ skip_w, const float* __restrict__ skip_b,
    const float* __restrict__ end1_w, const float* __restrict__ end1_b,
    const float* __restrict__ end2_w, const float* __restrict__ end2_b,
    const float* __restrict__ fc1_w,  const float* __restrict__ fc1_b,
    const float* __restrict__ fc2_w,  const float* __restrict__ fc2_b,
    const float* __restrict__ fc3_w,  const float* __restrict__ fc3_b,
    const float* __restrict__ fc4_w,  const float* __restrict__ fc4_b,
    float* __restrict__ out)
{
    extern __shared__ float sm[];
    __shared__ int stok[77];

    float* X  = sm + OFF_X;
    float* RB = sm + OFF_RB;
    float* GT = sm + OFF_GT;

    const int b    = blockIdx.x;
    const int tid  = threadIdx.x;
    const int lane = tid & 31;
    const int warp = tid >> 5;
    // compute warps 0..15: 8 channel groups of 4, 2 position groups
    const int cg   = warp & 7;
    const int pg   = (warp >> 3) & 1;
    const int cb   = cg * 4;
    const int u0   = lane + 32 * pg;   // 0..63
    const int u1   = u0 + 64;          // 64..127
    const int s    = tid - 512;        // staging thread id (warps 16-23)

    // ---- staging helper: layer li -> weight buffer bi (threads 512..767) ----
    auto stage = [&](int li, int bi) {
        float* B = sm + OFF_WB + bi * WBSZ;
        const float* gd = dil_w  + li * 2048;
        const float* gf = filt_w + li * 2048;
        const float* gg = gate_w + li * 2048;
        const float* gr = res_w  + li * 1024;
        #pragma unroll
        for (int k = 0; k < 8; k++) {
            int t = s + 256 * k;
            int c = t >> 6, rk = t & 63;
            int o = rk * XS + c;
            B[WDO + o] = __ldg(gd + t);
            B[WFO + o] = __ldg(gf + t);
            B[WGO + o] = __ldg(gg + t);
        }
        #pragma unroll
        for (int k = 0; k < 4; k++) {
            int t = s + 256 * k;
            B[WRO + (t & 31) * XS + (t >> 5)] = __ldg(gr + t);
        }
        if (s < 128) {
            int q = s >> 5, i = s & 31;
            const float* bp = (q == 0) ? dil_b : (q == 1) ? filt_b : (q == 2) ? gate_b : res_b;
            B[BSO + s] = __ldg(bp + li * 32 + i);
        }
    };

    // ================= init: split work between warp groups ===============
    if (warp < 16) {
        if (tid < 77) stok[tid] = tokens[b * T_LEN + (T_LEN - 77) + tid];
        float* WI = RB;                      // [e][c] stride XS (3600 fl, spills into GT scratch)
        for (int t = tid; t < 3200; t += 512)
            WI[(t % 100) * XS + (t / 100)] = init_w[t];
        asm volatile("bar.sync 1, 512;");
        float* SE = sm + OFF_WB + 2 * WBSZ;  // [p][e] stride SESTR in buf2 (8008 fl)
        for (int t = tid; t < 7700; t += 512) {
            int p = t / 100, e = t - p * 100;
            SE[p * SESTR + e] = emb[stok[p] * 100 + e];
        }
        asm volatile("bar.sync 1, 512;");
        {
            const int v1 = (u1 < 77);
            const int uu1 = v1 ? u1 : 0;
            u64 a0 = pack2(init_b[cb],   init_b[cb+1]);
            u64 a1 = pack2(init_b[cb+2], init_b[cb+3]);
            u64 b0 = a0, b1 = a1;
            const float* xr0 = &SE[u0  * SESTR];
            const float* xr1 = &SE[uu1 * SESTR];
            #pragma unroll 5
            for (int e = 0; e < 100; e += 4) {
                float4 x0 = *(const float4*)(xr0 + e);
                float4 x1 = *(const float4*)(xr1 + e);
                #pragma unroll
                for (int ee = 0; ee < 4; ee++) {
                    u64 d0 = dup2((&x0.x)[ee]);
                    u64 d1 = dup2((&x1.x)[ee]);
                    const float* w = &WI[(e + ee) * XS + cb];
                    ulonglong2 Wv = *(const ulonglong2*)w;
                    fma2(a0, Wv.x, d0); fma2(a1, Wv.y, d0);
                    fma2(b0, Wv.x, d1); fma2(b1, Wv.y, d1);
                }
            }
            { ulonglong2 t0; t0.x = a0; t0.y = a1; *(ulonglong2*)&X[u0*XS + cb] = t0; }
            if (v1) { ulonglong2 t0; t0.x = b0; t0.y = b1; *(ulonglong2*)&X[u1*XS + cb] = t0; }
        }
    } else {
        stage(0, 0);        // layer 0 -> buf0
        stage(1, 1);        // layer 1 -> buf1
    }
    __syncthreads();

    // ================= 16 dilated layers =================================
    int W = 75;
    int cur = 0;            // li % 3
    #pragma unroll 1
    for (int li = 0; li < 16; li++) {
        const int d = 1 << (li & 3);
        if (li) W -= d + 1;
        const bool dual = (W > 63);   // W values: {75,72,67} dual; rest single

        float* WB  = sm + OFF_WB + cur * WBSZ;
        const float* WD  = WB + WDO;
        const float* WF  = WB + WFO;
        const float* WG  = WB + WGO;
        const float* WRs = WB + WRO;
        const float* BS  = WB + BSO;

        // staging warps: prefetch layer li+2 while compute runs
        if (warp >= 16 && li < 14) {
            int bi = cur + 2; if (bi >= 3) bi -= 3;
            stage(li + 2, bi);
        }

        // ---- dilated conv -> RB, u in [0, W] ----
        if (warp < 16) {
            if (dual) {
                const int v1 = (u1 <= W);
                const int uu1 = v1 ? u1 : 0;
                u64 a0 = pack2(BS[cb], BS[cb+1]);
                u64 a1 = pack2(BS[cb+2], BS[cb+3]);
                u64 b0 = a0, b1 = a1;
                const float* p00 = &X[u0*XS];
                const float* p01 = &X[(u0 + d)*XS];
                const float* p10 = &X[uu1*XS];
                const float* p11 = &X[(uu1 + d)*XS];
                #pragma unroll
                for (int r = 0; r < 32; r += 4) {
                    float4 xa0 = *(const float4*)(p00 + r);
                    float4 xb0 = *(const float4*)(p01 + r);
                    float4 xa1 = *(const float4*)(p10 + r);
                    float4 xb1 = *(const float4*)(p11 + r);
                    #pragma unroll
                    for (int rr = 0; rr < 4; rr++) {
                        const float* w = &WD[(2*(r + rr))*XS + cb];
                        ulonglong2 W0 = *(const ulonglong2*)w;
                        ulonglong2 W1 = *(const ulonglong2*)(w + XS);
                        u64 d00 = dup2((&xa0.x)[rr]), d01 = dup2((&xb0.x)[rr]);
                        u64 d10 = dup2((&xa1.x)[rr]), d11 = dup2((&xb1.x)[rr]);
                        fma2(a0, W0.x, d00); fma2(a1, W0.y, d00);
                        fma2(a0, W1.x, d01); fma2(a1, W1.y, d01);
                        fma2(b0, W0.x, d10); fma2(b1, W0.y, d10);
                        fma2(b0, W1.x, d11); fma2(b1, W1.y, d11);
                    }
                }
                { ulonglong2 t0; t0.x = a0; t0.y = a1; *(ulonglong2*)&RB[u0*XS + cb] = t0; }
                if (v1) { ulonglong2 t0; t0.x = b0; t0.y = b1; *(ulonglong2*)&RB[u1*XS + cb] = t0; }
            } else if (32*pg <= W) {
                const int v0 = (u0 <= W);
                const int uu0 = v0 ? u0 : 0;
                u64 a0 = pack2(BS[cb], BS[cb+1]);
                u64 a1 = pack2(BS[cb+2], BS[cb+3]);
                u64 c0 = dup2(0.f), c1 = dup2(0.f);
                const float* p00 = &X[uu0*XS];
                const float* p01 = &X[(uu0 + d)*XS];
                #pragma unroll
                for (int r = 0; r < 32; r += 4) {
                    float4 xa = *(const float4*)(p00 + r);
                    float4 xb = *(const float4*)(p01 + r);
                    #pragma unroll
                    for (int rr = 0; rr < 4; rr++) {
                        const float* w = &WD[(2*(r + rr))*XS + cb];
                        ulonglong2 W0 = *(const ulonglong2*)w;
                        ulonglong2 W1 = *(const ulonglong2*)(w + XS);
                        u64 d00 = dup2((&xa.x)[rr]), d01 = dup2((&xb.x)[rr]);
                        fma2(a0, W0.x, d00); fma2(a1, W0.y, d00);
                        fma2(c0, W1.x, d01); fma2(c1, W1.y, d01);
                    }
                }
                if (v0) {
                    ulonglong2 t0; t0.x = add2(a0, c0); t0.y = add2(a1, c1);
                    *(ulonglong2*)&RB[u0*XS + cb] = t0;
                }
            }
        }
        __syncthreads();

        // ---- filter & gate convs + activation + product -> GT, u in [0, W) ----
        if (warp < 16) {
            if (dual) {
                const int v1 = (u1 < W);
                const int uu1 = v1 ? u1 : 0;
                u64 f0 = pack2(BS[32+cb], BS[32+cb+1]);
                u64 f1 = pack2(BS[32+cb+2], BS[32+cb+3]);
                u64 g0 = pack2(BS[64+cb], BS[64+cb+1]);
                u64 g1 = pack2(BS[64+cb+2], BS[64+cb+3]);
                u64 h0 = f0, h1 = f1;
                u64 k0 = g0, k1 = g1;
                const float* p00 = &RB[u0*XS];
                const float* p01 = &RB[(u0 + 1)*XS];
                const float* p10 = &RB[uu1*XS];
                const float* p11 = &RB[(uu1 + 1)*XS];
                #pragma unroll
                for (int r = 0; r < 32; r += 4) {
                    float4 xa0 = *(const float4*)(p00 + r);
                    float4 xb0 = *(const float4*)(p01 + r);
                    float4 xa1 = *(const float4*)(p10 + r);
                    float4 xb1 = *(const float4*)(p11 + r);
                    #pragma unroll
                    for (int rr = 0; rr < 4; rr++) {
                        u64 d00 = dup2((&xa0.x)[rr]), d01 = dup2((&xb0.x)[rr]);
                        u64 d10 = dup2((&xa1.x)[rr]), d11 = dup2((&xb1.x)[rr]);
                        const float* wf = &WF[(2*(r + rr))*XS + cb];
                        ulonglong2 F0 = *(const ulonglong2*)wf;
                        ulonglong2 F1 = *(const ulonglong2*)(wf + XS);
                        fma2(f0, F0.x, d00); fma2(f1, F0.y, d00);
                        fma2(f0, F1.x, d01); fma2(f1, F1.y, d01);
                        fma2(h0, F0.x, d10); fma2(h1, F0.y, d10);
                        fma2(h0, F1.x, d11); fma2(h1, F1.y, d11);
                        const float* wg = &WG[(2*(r + rr))*XS + cb];
                        ulonglong2 G0 = *(const ulonglong2*)wg;
                        ulonglong2 G1 = *(const ulonglong2*)(wg + XS);
                        fma2(g0, G0.x, d00); fma2(g1, G0.y, d00);
                        fma2(g0, G1.x, d01); fma2(g1, G1.y, d01);
                        fma2(k0, G0.x, d10); fma2(k1, G0.y, d10);
                        fma2(k0, G1.x, d11); fma2(k1, G1.y, d11);
                    }
                }
                {
                    float2 Fa = unpk(f0), Fb = unpk(f1);
                    float2 Ga = unpk(g0), Gb = unpk(g1);
                    float4 o;
                    o.x = fast_tanh(Fa.x) * fast_sig(Ga.x);
                    o.y = fast_tanh(Fa.y) * fast_sig(Ga.y);
                    o.z = fast_tanh(Fb.x) * fast_sig(Gb.x);
                    o.w = fast_tanh(Fb.y) * fast_sig(Gb.y);
                    *(float4*)&GT[u0*XS + cb] = o;
                }
                if (v1) {
                    float2 Fa = unpk(h0), Fb = unpk(h1);
                    float2 Ga = unpk(k0), Gb = unpk(k1);
                    float4 o;
                    o.x = fast_tanh(Fa.x) * fast_sig(Ga.x);
                    o.y = fast_tanh(Fa.y) * fast_sig(Ga.y);
                    o.z = fast_tanh(Fb.x) * fast_sig(Gb.x);
                    o.w = fast_tanh(Fb.y) * fast_sig(Gb.y);
                    *(float4*)&GT[u1*XS + cb] = o;
                }
            } else if (32*pg < W) {
                const int v0 = (u0 < W);
                const int uu0 = v0 ? u0 : 0;
                u64 f0 = pack2(BS[32+cb], BS[32+cb+1]);
                u64 f1 = pack2(BS[32+cb+2], BS[32+cb+3]);
                u64 g0 = pack2(BS[64+cb], BS[64+cb+1]);
                u64 g1 = pack2(BS[64+cb+2], BS[64+cb+3]);
                u64 h0 = dup2(0.f), h1 = dup2(0.f);
                u64 k0 = dup2(0.f), k1 = dup2(0.f);
                const float* p00 = &RB[uu0*XS];
                const float* p01 = &RB[(uu0 + 1)*XS];
                #pragma unroll
                for (int r = 0; r < 32; r += 4) {
                    float4 xa = *(const float4*)(p00 + r);
                    float4 xb = *(const float4*)(p01 + r);
                    #pragma unroll
                    for (int rr = 0; rr < 4; rr++) {
                        u64 d00 = dup2((&xa.x)[rr]), d01 = dup2((&xb.x)[rr]);
                        const float* wf = &WF[(2*(r + rr))*XS + cb];
                        ulonglong2 F0 = *(const ulonglong2*)wf;
                        ulonglong2 F1 = *(const ulonglong2*)(wf + XS);
                        fma2(f0, F0.x, d00); fma2(f1, F0.y, d00);
                        fma2(h0, F1.x, d01); fma2(h1, F1.y, d01);
                        const float* wg = &WG[(2*(r + rr))*XS + cb];
                        ulonglong2 G0 = *(const ulonglong2*)wg;
                        ulonglong2 G1 = *(const ulonglong2*)(wg + XS);
                        fma2(g0, G0.x, d00); fma2(g1, G0.y, d00);
                        fma2(k0, G1.x, d01); fma2(k1, G1.y, d01);
                    }
                }
                if (v0) {
                    f0 = add2(f0, h0); f1 = add2(f1, h1);
                    g0 = add2(g0, k0); g1 = add2(g1, k1);
                    float2 Fa = unpk(f0), Fb = unpk(f1);
                    float2 Ga = unpk(g0), Gb = unpk(g1);
                    float4 o;
                    o.x = fast_tanh(Fa.x) * fast_sig(Ga.x);
                    o.y = fast_tanh(Fa.y) * fast_sig(Ga.y);
                    o.z = fast_tanh(Fb.x) * fast_sig(Gb.x);
                    o.w = fast_tanh(Fb.y) * fast_sig(Gb.y);
                    *(float4*)&GT[u0*XS + cb] = o;
                }
            }
        }
        __syncthreads();

        // ---- res 1x1 conv + residual add -> X, u in [0, W) ----
        if (li < 15) {
            if (warp < 16) {
                if (dual) {
                    const int v1 = (u1 < W);
                    const int uu1 = v1 ? u1 : 0;
                    u64 a0 = pack2(BS[96+cb], BS[96+cb+1]);
                    u64 a1 = pack2(BS[96+cb+2], BS[96+cb+3]);
                    u64 b0 = a0, b1 = a1;
                    const float* p0 = &GT[u0*XS];
                    const float* p1 = &GT[uu1*XS];
                    #pragma unroll
                    for (int r = 0; r < 32; r += 4) {
                        float4 xa0 = *(const float4*)(p0 + r);
                        float4 xa1 = *(const float4*)(p1 + r);
                        #pragma unroll
                        for (int rr = 0; rr < 4; rr++) {
                            u64 d0 = dup2((&xa0.x)[rr]);
                            u64 d1 = dup2((&xa1.x)[rr]);
                            ulonglong2 Wv = *(const ulonglong2*)&WRs[(r + rr)*XS + cb];
                            fma2(a0, Wv.x, d0); fma2(a1, Wv.y, d0);
                            fma2(b0, Wv.x, d1); fma2(b1, Wv.y, d1);
                        }
                    }
                    {
                        ulonglong2 rv = *(const ulonglong2*)&RB[u0*XS + cb];
                        ulonglong2 t0; t0.x = add2(a0, rv.x); t0.y = add2(a1, rv.y);
                        *(ulonglong2*)&X[u0*XS + cb] = t0;
                    }
                    if (v1) {
                        ulonglong2 rv = *(const ulonglong2*)&RB[u1*XS + cb];
                        ulonglong2 t0; t0.x = add2(b0, rv.x); t0.y = add2(b1, rv.y);
                        *(ulonglong2*)&X[u1*XS + cb] = t0;
                    }
                } else if (32*pg < W) {
                    const int v0 = (u0 < W);
                    const int uu0 = v0 ? u0 : 0;
                    u64 a0 = pack2(BS[96+cb], BS[96+cb+1]);
                    u64 a1 = pack2(BS[96+cb+2], BS[96+cb+3]);
                    u64 c0 = dup2(0.f), c1 = dup2(0.f);
                    const float* p0 = &GT[uu0*XS];
                    #pragma unroll
                    for (int r = 0; r < 32; r += 8) {
                        float4 xa = *(const float4*)(p0 + r);
                        float4 xb = *(const float4*)(p0 + r + 4);
                        #pragma unroll
                        for (int rr = 0; rr < 4; rr++) {
                            u64 d0 = dup2((&xa.x)[rr]);
                            u64 d1 = dup2((&xb.x)[rr]);
                            ulonglong2 W0 = *(const ulonglong2*)&WRs[(r + rr)*XS + cb];
                            ulonglong2 W1 = *(const ulonglong2*)&WRs[(r + rr + 4)*XS + cb];
                            fma2(a0, W0.x, d0); fma2(a1, W0.y, d0);
                            fma2(c0, W1.x, d1); fma2(c1, W1.y, d1);
                        }
                    }
                    if (v0) {
                        ulonglong2 rv = *(const ulonglong2*)&RB[u0*XS + cb];
                        ulonglong2 t0;
                        t0.x = add2(add2(a0, c0), rv.x);
                        t0.y = add2(add2(a1, c1), rv.y);
                        *(ulonglong2*)&X[u0*XS + cb] = t0;
                    }
                }
            }
            __syncthreads();
        }
        cur++; if (cur == 3) cur = 0;
    }

    // ================= tail: skip/end/fc at t = T-1 only =================
    float* SV = RB;        // relu(skip) 256
    float* H1 = RB + 256;  // 256
    float* H2 = RB + 512;  // 256
    float* F1 = RB + 768;  // 128
    float* F2 = RB + 896;  // 128
    float* F3 = RB + 1024; // 64

    const float* skw = skip_w + 15*256*32;
    const float* skb = skip_b + 15*256;
    float gv = GT[lane];
    #pragma unroll 2
    for (int o = warp; o < 256; o += 24) {
        float v = __ldg(&skw[o*32 + lane]) * gv;
        v = warp_sum(v);
        if (lane == 0) SV[o] = fmaxf(v + skb[o], 0.f);
    }
    __syncthreads();
    #pragma unroll 2
    for (int o = warp; o < 256; o += 24) {
        const float4* wp = (const float4*)(end1_w + o*256);
        const float4* sp = (const float4*)SV;
        float v = dot4(__ldg(wp + lane), sp[lane]) + dot4(__ldg(wp + lane + 32), sp[lane + 32]);
        v = warp_sum(v);
        if (lane == 0) H1[o] = fmaxf(v + end1_b[o], 0.f);
    }
    __syncthreads();
    #pragma unroll 2
    for (int o = warp; o < 256; o += 24) {
        const float4* wp = (const float4*)(end2_w + o*256);
        const float4* sp = (const float4*)H1;
        float v = dot4(__ldg(wp + lane), sp[lane]) + dot4(__ldg(wp + lane + 32), sp[lane + 32]);
        v = warp_sum(v);
        if (lane == 0) H2[o] = v + end2_b[o];
    }
    __syncthreads();
    #pragma unroll 2
    for (int o = warp; o < 128; o += 24) {
        const float4* wp = (const float4*)(fc1_w + o*256);
        const float4* sp = (const float4*)H2;
        float v = dot4(__ldg(wp + lane), sp[lane]) + dot4(__ldg(wp + lane + 32), sp[lane + 32]);
        v = warp_sum(v);
        if (lane == 0) F1[o] = fmaxf(v + fc1_b[o], 0.f);
    }
    __syncthreads();
    #pragma unroll 2
    for (int o = warp; o < 128; o += 24) {
        const float4* wp = (const float4*)(fc2_w + o*128);
        const float4* sp = (const float4*)F1;
        float v = dot4(__ldg(wp + lane), sp[lane]);
        v = warp_sum(v);
        if (lane == 0) F2[o] = fmaxf(v + fc2_b[o], 0.f);
    }
    __syncthreads();
    #pragma unroll 2
    for (int o = warp; o < 64; o += 24) {
        const float4* wp = (const float4*)(fc3_w + o*128);
        const float4* sp = (const float4*)F2;
        float v = dot4(__ldg(wp + lane), sp[lane]);
        v = warp_sum(v);
        if (lane == 0) F3[o] = fmaxf(v + fc3_b[o], 0.f);
    }
    __syncthreads();
    #pragma unroll 2
    for (int o = warp; o < 256; o += 24) {
        const float2* wp = (const float2*)(fc4_w + o*64);
        const float2* sp = (const float2*)F3;
        float2 wv = __ldg(wp + lane);
        float2 sv = sp[lane];
        float v = fmaf(wv.x, sv.x, wv.y * sv.y);
        v = warp_sum(v);
        if (lane == 0) out[b*256 + o] = v + fc4_b[o];
    }
}

extern "C" void kernel_launch(void* const* d_in, const int* in_sizes, int n_in,
                              void* d_out, int out_size)
{
    (void)in_sizes; (void)n_in; (void)out_size;
    const size_t smem_bytes = (size_t)SMEM_FLOATS * sizeof(float);
    cudaFuncSetAttribute(wavenet_kernel, cudaFuncAttributeMaxDynamicSharedMemorySize,
                         (int)smem_bytes);
    wavenet_kernel<<<16, NT, smem_bytes>>>(
        (const int*)  d_in[0],  (const float*)d_in[1],
        (const float*)d_in[2],  (const float*)d_in[3],
        (const float*)d_in[4],  (const float*)d_in[5],
        (const float*)d_in[6],  (const float*)d_in[7],
        (const float*)d_in[8],  (const float*)d_in[9],
        (const float*)d_in[10], (const float*)d_in[11],
        (const float*)d_in[12], (const float*)d_in[13],
        (const float*)d_in[14], (const float*)d_in[15],
        (const float*)d_in[16], (const float*)d_in[17],
        (const float*)d_in[18], (const float*)d_in[19],
        (const float*)d_in[20], (const float*)d_in[21],
        (const float*)d_in[22], (const float*)d_in[23],
        (const float*)d_in[24], (const float*)d_in[25],
        (float*)d_out);
}

// round 8
// speedup vs baseline: 1.2417x; 1.0550x over previous
#include <cuda_runtime.h>
#include <math.h>

#define T_LEN 8192
#define NT 768
#define XS 36          // padded row stride: 16B-aligned, phase-conflict-free (4-word rotation)
#define SESTR 104

// float offsets in dynamic smem
#define OFF_X   0          // 77 x XS
#define OFF_RB  2772       // 76 x XS
#define OFF_GT  5508       // 75 x XS
#define OFF_WB  8208       // 3 weight buffers of WBSZ
#define WBSZ    8192
// inside a weight buffer
#define WDO 0              // 64 x XS
#define WFO 2304
#define WGO 4608
#define WRO 6912           // 32 x XS
#define BSO 8064           // 128 biases
#define SMEM_FLOATS (OFF_WB + 3*WBSZ)   // 32784 floats = 131136 B

typedef unsigned long long u64;

__device__ __forceinline__ u64 pack2(float lo, float hi) {
    u64 r; asm("mov.b64 %0,{%1,%2};" : "=l"(r) : "f"(lo), "f"(hi)); return r;
}
__device__ __forceinline__ u64 dup2(float x) { return pack2(x, x); }
__device__ __forceinline__ void fma2(u64& a, u64 w, u64 x) {
    asm("fma.rn.f32x2 %0,%1,%2,%0;" : "+l"(a) : "l"(w), "l"(x));
}
__device__ __forceinline__ u64 add2(u64 a, u64 b) {
    u64 r; asm("add.rn.f32x2 %0,%1,%2;" : "=l"(r) : "l"(a), "l"(b)); return r;
}
__device__ __forceinline__ float2 unpk(u64 a) {
    float2 f; asm("mov.b64 {%0,%1},%2;" : "=f"(f.x), "=f"(f.y) : "l"(a)); return f;
}
__device__ __forceinline__ float warp_sum(float v) {
    #pragma unroll
    for (int o = 16; o; o >>= 1) v += __shfl_xor_sync(0xffffffffu, v, o);
    return v;
}
__device__ __forceinline__ float fast_tanh(float x) {
    float e = __expf(-2.0f * x);
    return fmaf(2.0f, __frcp_rn(1.0f + e), -1.0f);
}
__device__ __forceinline__ float fast_sig(float x) {
    return __frcp_rn(1.0f + __expf(-x));
}
__device__ __forceinline__ float dot4(float4 a, float4 b) {
    return fmaf(a.x, b.x, fmaf(a.y, b.y, fmaf(a.z, b.z, a.w * b.w)));
}

__global__ void __launch_bounds__(NT, 1) wavenet_kernel(
    const int*   __restrict__ tokens,
    const float* __restrict__ emb,
    const float* __restrict__ init_w, const float* __restrict__ init_b,
    const float* __restrict__ dil_w,  const float* __restrict__ dil_b,
    const float* __restrict__ filt_w, const float* __restrict__ filt_b,
    const float* __restrict__ gate_w, const float* __restrict__ gate_b,
    const float* __restrict__ res_w,  const float* __restrict__ res_b,
    const float* __restrict__ skip_w, const float* __restrict__ skip_b,
    const float* __restrict__ end1_w, const float* __restrict__ end1_b,
    const float* __restrict__ end2_w, const float* __restrict__ end2_b,
    const float* __restrict__ fc1_w,  const float* __restrict__ fc1_b,
    const float* __restrict__ fc2_w,  const float* __restrict__ fc2_b,
    const float* __restrict__ fc3_w,  const float* __restrict__ fc3_b,
    const float* __restrict__ fc4_w,  const float* __restrict__ fc4_b,
    float* __restrict__ out)
{
    extern __shared__ float sm[];
    __shared__ int stok[77];

    float* X  = sm + OFF_X;
    float* RB = sm + OFF_RB;
    float* GT = sm + OFF_GT;

    const int b    = blockIdx.x;
    const int tid  = threadIdx.x;
    const int lane = tid & 31;
    const int warp = tid >> 5;
    const int cg   = warp & 7;          // 8 channel groups of 4
    const int pg   = (warp >> 3) & 1;
    const int cb   = cg * 4;
    const int s    = tid - 512;         // staging thread id (warps 16-23)

    // ---- staging helper: layer li -> weight buffer bi (threads 512..767) ----
    auto stage = [&](int li, int bi) {
        float* B = sm + OFF_WB + bi * WBSZ;
        const float* gd = dil_w  + li * 2048;
        const float* gf = filt_w + li * 2048;
        const float* gg = gate_w + li * 2048;
        const float* gr = res_w  + li * 1024;
        #pragma unroll
        for (int k = 0; k < 8; k++) {
            int t = s + 256 * k;
            int c = t >> 6, rk = t & 63;
            int o = rk * XS + c;
            B[WDO + o] = __ldg(gd + t);
            B[WFO + o] = __ldg(gf + t);
            B[WGO + o] = __ldg(gg + t);
        }
        #pragma unroll
        for (int k = 0; k < 4; k++) {
            int t = s + 256 * k;
            B[WRO + (t & 31) * XS + (t >> 5)] = __ldg(gr + t);
        }
        if (s < 128) {
            int q = s >> 5, i = s & 31;
            const float* bp = (q == 0) ? dil_b : (q == 1) ? filt_b : (q == 2) ? gate_b : res_b;
            B[BSO + s] = __ldg(bp + li * 32 + i);
        }
    };

    // ================= init: split work between warp groups ===============
    if (warp < 16) {
        const int iu0 = lane + 32 * pg;
        const int iu1 = iu0 + 64;
        if (tid < 77) stok[tid] = tokens[b * T_LEN + (T_LEN - 77) + tid];
        float* WI = RB;                      // [e][c] stride XS
        for (int t = tid; t < 3200; t += 512)
            WI[(t % 100) * XS + (t / 100)] = init_w[t];
        asm volatile("bar.sync 1, 512;");
        float* SE = sm + OFF_WB + 2 * WBSZ;  // [p][e] stride SESTR in buf2
        for (int t = tid; t < 7700; t += 512) {
            int p = t / 100, e = t - p * 100;
            SE[p * SESTR + e] = emb[stok[p] * 100 + e];
        }
        asm volatile("bar.sync 1, 512;");
        {
            const int v1 = (iu1 < 77);
            const int uu1 = v1 ? iu1 : 0;
            u64 a0 = pack2(init_b[cb],   init_b[cb+1]);
            u64 a1 = pack2(init_b[cb+2], init_b[cb+3]);
            u64 b0 = a0, b1 = a1;
            const float* xr0 = &SE[iu0 * SESTR];
            const float* xr1 = &SE[uu1 * SESTR];
            #pragma unroll 5
            for (int e = 0; e < 100; e += 4) {
                float4 x0 = *(const float4*)(xr0 + e);
                float4 x1 = *(const float4*)(xr1 + e);
                #pragma unroll
                for (int ee = 0; ee < 4; ee++) {
                    u64 d0 = dup2((&x0.x)[ee]);
                    u64 d1 = dup2((&x1.x)[ee]);
                    const float* w = &WI[(e + ee) * XS + cb];
                    ulonglong2 Wv = *(const ulonglong2*)w;
                    fma2(a0, Wv.x, d0); fma2(a1, Wv.y, d0);
                    fma2(b0, Wv.x, d1); fma2(b1, Wv.y, d1);
                }
            }
            { ulonglong2 t0; t0.x = a0; t0.y = a1; *(ulonglong2*)&X[iu0*XS + cb] = t0; }
            if (v1) { ulonglong2 t0; t0.x = b0; t0.y = b1; *(ulonglong2*)&X[iu1*XS + cb] = t0; }
        }
    } else {
        stage(0, 0);        // layer 0 -> buf0
        stage(1, 1);        // layer 1 -> buf1
    }
    __syncthreads();

    // ================= 16 dilated layers =================================
    int W = 75;
    int cur = 0;            // li % 3
    #pragma unroll 1
    for (int li = 0; li < 16; li++) {
        const int d = 1 << (li & 3);
        if (li) W -= d + 1;
        // mode 0: W>63 dual 16 warps; mode 1: 31<W<=63 dual 8 warps; mode 2: W<=31 single 8 warps
        const int mode = (W > 63) ? 0 : ((W > 31) ? 1 : 2);

        float* WB  = sm + OFF_WB + cur * WBSZ;
        const float* WD  = WB + WDO;
        const float* WF  = WB + WFO;
        const float* WG  = WB + WGO;
        const float* WRs = WB + WRO;
        const float* BS  = WB + BSO;

        // staging warps: prefetch layer li+2 while compute runs
        if (warp >= 16 && li < 14) {
            int bi = cur + 2; if (bi >= 3) bi -= 3;
            stage(li + 2, bi);
        }

        const bool dualAct = (mode == 0) ? (warp < 16) : (mode == 1 && warp < 8);
        const int U0 = (mode == 0) ? (lane + 32 * pg) : lane;
        const int U1 = U0 + ((mode == 0) ? 64 : 32);

        // ---- dilated conv -> RB ----
        if (dualAct) {
            const int v1 = (U1 <= W);
            const int uu1 = v1 ? U1 : 0;
            u64 a0 = pack2(BS[cb], BS[cb+1]);
            u64 a1 = pack2(BS[cb+2], BS[cb+3]);
            u64 b0 = a0, b1 = a1;
            const float* p00 = &X[U0*XS];
            const float* p01 = &X[(U0 + d)*XS];
            const float* p10 = &X[uu1*XS];
            const float* p11 = &X[(uu1 + d)*XS];
            #pragma unroll
            for (int r = 0; r < 32; r += 4) {
                float4 xa0 = *(const float4*)(p00 + r);
                float4 xb0 = *(const float4*)(p01 + r);
                float4 xa1 = *(const float4*)(p10 + r);
                float4 xb1 = *(const float4*)(p11 + r);
                #pragma unroll
                for (int rr = 0; rr < 4; rr++) {
                    const float* w = &WD[(2*(r + rr))*XS + cb];
                    ulonglong2 W0 = *(const ulonglong2*)w;
                    ulonglong2 W1 = *(const ulonglong2*)(w + XS);
                    u64 d00 = dup2((&xa0.x)[rr]), d01 = dup2((&xb0.x)[rr]);
                    u64 d10 = dup2((&xa1.x)[rr]), d11 = dup2((&xb1.x)[rr]);
                    fma2(a0, W0.x, d00); fma2(a1, W0.y, d00);
                    fma2(a0, W1.x, d01); fma2(a1, W1.y, d01);
                    fma2(b0, W0.x, d10); fma2(b1, W0.y, d10);
                    fma2(b0, W1.x, d11); fma2(b1, W1.y, d11);
                }
            }
            { ulonglong2 t0; t0.x = a0; t0.y = a1; *(ulonglong2*)&RB[U0*XS + cb] = t0; }
            if (v1) { ulonglong2 t0; t0.x = b0; t0.y = b1; *(ulonglong2*)&RB[U1*XS + cb] = t0; }
        } else if (mode == 2 && warp < 8) {
            const int u = lane;
            const int v0 = (u <= W);
            const int uu0 = v0 ? u : 0;
            u64 a0 = pack2(BS[cb], BS[cb+1]);
            u64 a1 = pack2(BS[cb+2], BS[cb+3]);
            u64 c0 = dup2(0.f), c1 = dup2(0.f);
            const float* p00 = &X[uu0*XS];
            const float* p01 = &X[(uu0 + d)*XS];
            #pragma unroll
            for (int r = 0; r < 32; r += 4) {
                float4 xa = *(const float4*)(p00 + r);
                float4 xb = *(const float4*)(p01 + r);
                #pragma unroll
                for (int rr = 0; rr < 4; rr++) {
                    const float* w = &WD[(2*(r + rr))*XS + cb];
                    ulonglong2 W0 = *(const ulonglong2*)w;
                    ulonglong2 W1 = *(const ulonglong2*)(w + XS);
                    u64 d00 = dup2((&xa.x)[rr]), d01 = dup2((&xb.x)[rr]);
                    fma2(a0, W0.x, d00); fma2(a1, W0.y, d00);
                    fma2(c0, W1.x, d01); fma2(c1, W1.y, d01);
                }
            }
            if (v0) {
                ulonglong2 t0; t0.x = add2(a0, c0); t0.y = add2(a1, c1);
                *(ulonglong2*)&RB[u*XS + cb] = t0;
            }
        }
        __syncthreads();

        // ---- filter & gate convs + activation + product -> GT ----
        if (dualAct) {
            const int v1 = (U1 < W);
            const int uu1 = v1 ? U1 : 0;
            u64 f0 = pack2(BS[32+cb], BS[32+cb+1]);
            u64 f1 = pack2(BS[32+cb+2], BS[32+cb+3]);
            u64 g0 = pack2(BS[64+cb], BS[64+cb+1]);
            u64 g1 = pack2(BS[64+cb+2], BS[64+cb+3]);
            u64 h0 = f0, h1 = f1;
            u64 k0 = g0, k1 = g1;
            const float* p00 = &RB[U0*XS];
            const float* p01 = &RB[(U0 + 1)*XS];
            const float* p10 = &RB[uu1*XS];
            const float* p11 = &RB[(uu1 + 1)*XS];
            #pragma unroll
            for (int r = 0; r < 32; r += 4) {
                float4 xa0 = *(const float4*)(p00 + r);
                float4 xb0 = *(const float4*)(p01 + r);
                float4 xa1 = *(const float4*)(p10 + r);
                float4 xb1 = *(const float4*)(p11 + r);
                #pragma unroll
                for (int rr = 0; rr < 4; rr++) {
                    u64 d00 = dup2((&xa0.x)[rr]), d01 = dup2((&xb0.x)[rr]);
                    u64 d10 = dup2((&xa1.x)[rr]), d11 = dup2((&xb1.x)[rr]);
                    const float* wf = &WF[(2*(r + rr))*XS + cb];
                    ulonglong2 F0 = *(const ulonglong2*)wf;
                    ulonglong2 F1 = *(const ulonglong2*)(wf + XS);
                    fma2(f0, F0.x, d00); fma2(f1, F0.y, d00);
                    fma2(f0, F1.x, d01); fma2(f1, F1.y, d01);
                    fma2(h0, F0.x, d10); fma2(h1, F0.y, d10);
                    fma2(h0, F1.x, d11); fma2(h1, F1.y, d11);
                    const float* wg = &WG[(2*(r + rr))*XS + cb];
                    ulonglong2 G0 = *(const ulonglong2*)wg;
                    ulonglong2 G1 = *(const ulonglong2*)(wg + XS);
                    fma2(g0, G0.x, d00); fma2(g1, G0.y, d00);
                    fma2(g0, G1.x, d01); fma2(g1, G1.y, d01);
                    fma2(k0, G0.x, d10); fma2(k1, G0.y, d10);
                    fma2(k0, G1.x, d11); fma2(k1, G1.y, d11);
                }
            }
            {
                float2 Fa = unpk(f0), Fb = unpk(f1);
                float2 Ga = unpk(g0), Gb = unpk(g1);
                float4 o;
                o.x = fast_tanh(Fa.x) * fast_sig(Ga.x);
                o.y = fast_tanh(Fa.y) * fast_sig(Ga.y);
                o.z = fast_tanh(Fb.x) * fast_sig(Gb.x);
                o.w = fast_tanh(Fb.y) * fast_sig(Gb.y);
                *(float4*)&GT[U0*XS + cb] = o;
            }
            if (v1) {
                float2 Fa = unpk(h0), Fb = unpk(h1);
                float2 Ga = unpk(k0), Gb = unpk(k1);
                float4 o;
                o.x = fast_tanh(Fa.x) * fast_sig(Ga.x);
                o.y = fast_tanh(Fa.y) * fast_sig(Ga.y);
                o.z = fast_tanh(Fb.x) * fast_sig(Gb.x);
                o.w = fast_tanh(Fb.y) * fast_sig(Gb.y);
                *(float4*)&GT[U1*XS + cb] = o;
            }
        } else if (mode == 2 && warp < 8) {
            const int u = lane;
            const int v0 = (u < W);
            const int uu0 = v0 ? u : 0;
            u64 f0 = pack2(BS[32+cb], BS[32+cb+1]);
            u64 f1 = pack2(BS[32+cb+2], BS[32+cb+3]);
            u64 g0 = pack2(BS[64+cb], BS[64+cb+1]);
            u64 g1 = pack2(BS[64+cb+2], BS[64+cb+3]);
            u64 h0 = dup2(0.f), h1 = dup2(0.f);
            u64 k0 = dup2(0.f), k1 = dup2(0.f);
            const float* p00 = &RB[uu0*XS];
            const float* p01 = &RB[(uu0 + 1)*XS];
            #pragma unroll
            for (int r = 0; r < 32; r += 4) {
                float4 xa = *(const float4*)(p00 + r);
                float4 xb = *(const float4*)(p01 + r);
                #pragma unroll
                for (int rr = 0; rr < 4; rr++) {
                    u64 d00 = dup2((&xa.x)[rr]), d01 = dup2((&xb.x)[rr]);
                    const float* wf = &WF[(2*(r + rr))*XS + cb];
                    ulonglong2 F0 = *(const ulonglong2*)wf;
                    ulonglong2 F1 = *(const ulonglong2*)(wf + XS);
                    fma2(f0, F0.x, d00); fma2(f1, F0.y, d00);
                    fma2(h0, F1.x, d01); fma2(h1, F1.y, d01);
                    const float* wg = &WG[(2*(r + rr))*XS + cb];
                    ulonglong2 G0 = *(const ulonglong2*)wg;
                    ulonglong2 G1 = *(const ulonglong2*)(wg + XS);
                    fma2(g0, G0.x, d00); fma2(g1, G0.y, d00);
                    fma2(k0, G1.x, d01); fma2(k1, G1.y, d01);
                }
            }
            if (v0) {
                f0 = add2(f0, h0); f1 = add2(f1, h1);
                g0 = add2(g0, k0); g1 = add2(g1, k1);
                float2 Fa = unpk(f0), Fb = unpk(f1);
                float2 Ga = unpk(g0), Gb = unpk(g1);
                float4 o;
                o.x = fast_tanh(Fa.x) * fast_sig(Ga.x);
                o.y = fast_tanh(Fa.y) * fast_sig(Ga.y);
                o.z = fast_tanh(Fb.x) * fast_sig(Gb.x);
                o.w = fast_tanh(Fb.y) * fast_sig(Gb.y);
                *(float4*)&GT[u*XS + cb] = o;
            }
        }
        __syncthreads();

        // ---- res 1x1 conv + residual add -> X ----
        if (li < 15) {
            if (dualAct) {
                const int v1 = (U1 < W);
                const int uu1 = v1 ? U1 : 0;
                u64 a0 = pack2(BS[96+cb], BS[96+cb+1]);
                u64 a1 = pack2(BS[96+cb+2], BS[96+cb+3]);
                u64 b0 = a0, b1 = a1;
                const float* p0 = &GT[U0*XS];
                const float* p1 = &GT[uu1*XS];
                #pragma unroll
                for (int r = 0; r < 32; r += 4) {
                    float4 xa0 = *(const float4*)(p0 + r);
                    float4 xa1 = *(const float4*)(p1 + r);
                    #pragma unroll
                    for (int rr = 0; rr < 4; rr++) {
                        u64 d0 = dup2((&xa0.x)[rr]);
                        u64 d1 = dup2((&xa1.x)[rr]);
                        ulonglong2 Wv = *(const ulonglong2*)&WRs[(r + rr)*XS + cb];
                        fma2(a0, Wv.x, d0); fma2(a1, Wv.y, d0);
                        fma2(b0, Wv.x, d1); fma2(b1, Wv.y, d1);
                    }
                }
                {
                    ulonglong2 rv = *(const ulonglong2*)&RB[U0*XS + cb];
                    ulonglong2 t0; t0.x = add2(a0, rv.x); t0.y = add2(a1, rv.y);
                    *(ulonglong2*)&X[U0*XS + cb] = t0;
                }
                if (v1) {
                    ulonglong2 rv = *(const ulonglong2*)&RB[U1*XS + cb];
                    ulonglong2 t0; t0.x = add2(b0, rv.x); t0.y = add2(b1, rv.y);
                    *(ulonglong2*)&X[U1*XS + cb] = t0;
                }
            } else if (mode == 2 && warp < 8) {
                const int u = lane;
                const int v0 = (u < W);
                const int uu0 = v0 ? u : 0;
                u64 a0 = pack2(BS[96+cb], BS[96+cb+1]);
                u64 a1 = pack2(BS[96+cb+2], BS[96+cb+3]);
                u64 c0 = dup2(0.f), c1 = dup2(0.f);
                const float* p0 = &GT[uu0*XS];
                #pragma unroll
                for (int r = 0; r < 32; r += 8) {
                    float4 xa = *(const float4*)(p0 + r);
                    float4 xb = *(const float4*)(p0 + r + 4);
                    #pragma unroll
                    for (int rr = 0; rr < 4; rr++) {
                        u64 d0 = dup2((&xa.x)[rr]);
                        u64 d1 = dup2((&xb.x)[rr]);
                        ulonglong2 W0 = *(const ulonglong2*)&WRs[(r + rr)*XS + cb];
                        ulonglong2 W1 = *(const ulonglong2*)&WRs[(r + rr + 4)*XS + cb];
                        fma2(a0, W0.x, d0); fma2(a1, W0.y, d0);
                        fma2(c0, W1.x, d1); fma2(c1, W1.y, d1);
                    }
                }
                if (v0) {
                    ulonglong2 rv = *(const ulonglong2*)&RB[u*XS + cb];
                    ulonglong2 t0;
                    t0.x = add2(add2(a0, c0), rv.x);
                    t0.y = add2(add2(a1, c1), rv.y);
                    *(ulonglong2*)&X[u*XS + cb] = t0;
                }
            }
            __syncthreads();
        }
        cur++; if (cur == 3) cur = 0;
    }

    // ================= tail: skip/end/fc at t = T-1 only =================
    float* SV = RB;        // relu(skip) 256
    float* H1 = RB + 256;  // 256
    float* H2 = RB + 512;  // 256
    float* F1 = RB + 768;  // 128
    float* F2 = RB + 896;  // 128
    float* F3 = RB + 1024; // 64

    const float* skw = skip_w + 15*256*32;
    const float* skb = skip_b + 15*256;
    float gv = GT[lane];
    #pragma unroll 2
    for (int o = warp; o < 256; o += 24) {
        float v = __ldg(&skw[o*32 + lane]) * gv;
        v = warp_sum(v);
        if (lane == 0) SV[o] = fmaxf(v + skb[o], 0.f);
    }
    __syncthreads();
    #pragma unroll 2
    for (int o = warp; o < 256; o += 24) {
        const float4* wp = (const float4*)(end1_w + o*256);
        const float4* sp = (const float4*)SV;
        float v = dot4(__ldg(wp + lane), sp[lane]) + dot4(__ldg(wp + lane + 32), sp[lane + 32]);
        v = warp_sum(v);
        if (lane == 0) H1[o] = fmaxf(v + end1_b[o], 0.f);
    }
    __syncthreads();
    #pragma unroll 2
    for (int o = warp; o < 256; o += 24) {
        const float4* wp = (const float4*)(end2_w + o*256);
        const float4* sp = (const float4*)H1;
        float v = dot4(__ldg(wp + lane), sp[lane]) + dot4(__ldg(wp + lane + 32), sp[lane + 32]);
        v = warp_sum(v);
        if (lane == 0) H2[o] = v + end2_b[o];
    }
    __syncthreads();
    #pragma unroll 2
    for (int o = warp; o < 128; o += 24) {
        const float4* wp = (const float4*)(fc1_w + o*256);
        const float4* sp = (const float4*)H2;
        float v = dot4(__ldg(wp + lane), sp[lane]) + dot4(__ldg(wp + lane + 32), sp[lane + 32]);
        v = warp_sum(v);
        if (lane == 0) F1[o] = fmaxf(v + fc1_b[o], 0.f);
    }
    __syncthreads();
    #pragma unroll 2
    for (int o = warp; o < 128; o += 24) {
        const float4* wp = (const float4*)(fc2_w + o*128);
        const float4* sp = (const float4*)F1;
        float v = dot4(__ldg(wp + lane), sp[lane]);
        v = warp_sum(v);
        if (lane == 0) F2[o] = fmaxf(v + fc2_b[o], 0.f);
    }
    __syncthreads();
    #pragma unroll 2
    for (int o = warp; o < 64; o += 24) {
        const float4* wp = (const float4*)(fc3_w + o*128);
        const float4* sp = (const float4*)F2;
        float v = dot4(__ldg(wp + lane), sp[lane]);
        v = warp_sum(v);
        if (lane == 0) F3[o] = fmaxf(v + fc3_b[o], 0.f);
    }
    __syncthreads();
    #pragma unroll 2
    for (int o = warp; o < 256; o += 24) {
        const float2* wp = (const float2*)(fc4_w + o*64);
        const float2* sp = (const float2*)F3;
        float2 wv = __ldg(wp + lane);
        float2 sv = sp[lane];
        float v = fmaf(wv.x, sv.x, wv.y * sv.y);
        v = warp_sum(v);
        if (lane == 0) out[b*256 + o] = v + fc4_b[o];
    }
}

extern "C" void kernel_launch(void* const* d_in, const int* in_sizes, int n_in,
                              void* d_out, int out_size)
{
    (void)in_sizes; (void)n_in; (void)out_size;
    const size_t smem_bytes = (size_t)SMEM_FLOATS * sizeof(float);
    cudaFuncSetAttribute(wavenet_kernel, cudaFuncAttributeMaxDynamicSharedMemorySize,
                         (int)smem_bytes);
    wavenet_kernel<<<16, NT, smem_bytes>>>(
        (const int*)  d_in[0],  (const float*)d_in[1],
        (const float*)d_in[2],  (const float*)d_in[3],
        (const float*)d_in[4],  (const float*)d_in[5],
        (const float*)d_in[6],  (const float*)d_in[7],
        (const float*)d_in[8],  (const float*)d_in[9],
        (const float*)d_in[10], (const float*)d_in[11],
        (const float*)d_in[12], (const float*)d_in[13],
        (const float*)d_in[14], (const float*)d_in[15],
        (const float*)d_in[16], (const float*)d_in[17],
        (const float*)d_in[18], (const float*)d_in[19],
        (const float*)d_in[20], (const float*)d_in[21],
        (const float*)d_in[22], (const float*)d_in[23],
        (const float*)d_in[24], (const float*)d_in[25],
        (float*)d_out);
}